// round 2
// baseline (speedup 1.0000x reference)
#include <cuda_runtime.h>
#include <cuda_bf16.h>

#define BATCH 8192
#define DIM 10

// Scratch for pooled features [B, 10] (no cudaMalloc allowed).
__device__ float g_pooled[BATCH * DIM];

// ---------------------------------------------------------------------------
// Kernel 1: pooled[b,:] = (sum_n w_n * x[b,n,:]) @ W
// w_n = 0.125 * ([1,1,2] + A[0,n] + A[1,n])   (adj = 0.25*(off+A), avg rows 0,1)
// ---------------------------------------------------------------------------
__global__ void pooled_kernel(const float* __restrict__ x,
                              const float* __restrict__ A,
                              const float* __restrict__ W) {
    __shared__ float sW[DIM * DIM];
    __shared__ float sw[3];
    int tid = threadIdx.x;
    if (tid < DIM * DIM) sW[tid] = W[tid];
    if (tid < 3) {
        const float offsum[3] = {1.f, 1.f, 2.f};
        sw[tid] = 0.125f * (offsum[tid] + A[tid] + A[3 + tid]);
    }
    __syncthreads();

    int b = blockIdx.x * blockDim.x + threadIdx.x;
    if (b < BATCH) {
        const float* xb = x + b * 3 * DIM;
        float y[DIM];
        float w0 = sw[0], w1 = sw[1], w2 = sw[2];
        #pragma unroll
        for (int f = 0; f < DIM; f++)
            y[f] = fmaf(w2, xb[2 * DIM + f], fmaf(w1, xb[DIM + f], w0 * xb[f]));
        #pragma unroll
        for (int o = 0; o < DIM; o++) {
            float acc = 0.f;
            #pragma unroll
            for (int f = 0; f < DIM; f++)
                acc = fmaf(y[f], sW[f * DIM + o], acc);
            g_pooled[b * DIM + o] = acc;
        }
    }
}

// ---------------------------------------------------------------------------
// Kernel 2: fused attention  out = softmax(P P^T) P, never materializing S.
// CTA: 256 threads = 32 queries x 8 key-parts. Keys streamed via SMEM tiles.
// softmax computed without max-subtraction (shift-invariant; |s| small here).
// ---------------------------------------------------------------------------
#define BQ 32      // queries per CTA
#define PARTS 8    // threads per query
#define TILE 1024  // keys per SMEM tile
#define NTHREADS 256

__global__ __launch_bounds__(NTHREADS)
void attn_kernel(float* __restrict__ out) {
    __shared__ float sk[TILE * DIM];   // 40 KB
    __shared__ float sq[BQ * DIM];     // 1.25 KB

    int tid = threadIdx.x;
    int q0  = blockIdx.x * BQ;

    // stage this CTA's queries
    for (int i = tid; i < BQ * DIM; i += NTHREADS)
        sq[i] = g_pooled[q0 * DIM + i];
    __syncthreads();

    int qi = tid >> 3;    // 0..31
    int p  = tid & 7;     // 0..7

    float q[DIM];
    #pragma unroll
    for (int f = 0; f < DIM; f++) q[f] = sq[qi * DIM + f];

    float acc[DIM];
    #pragma unroll
    for (int f = 0; f < DIM; f++) acc[f] = 0.f;
    float esum = 0.f;

    for (int t = 0; t < BATCH; t += TILE) {
        __syncthreads();  // protect sk from previous iteration readers
        for (int i = tid; i < TILE * DIM; i += NTHREADS)
            sk[i] = g_pooled[t * DIM + i];
        __syncthreads();

        #pragma unroll 4
        for (int j = p; j < TILE; j += PARTS) {
            const float* kr = &sk[j * DIM];
            float s = 0.f;
            #pragma unroll
            for (int f = 0; f < DIM; f++) s = fmaf(q[f], kr[f], s);
            float e = __expf(s);
            esum += e;
            #pragma unroll
            for (int f = 0; f < DIM; f++) acc[f] = fmaf(e, kr[f], acc[f]);
        }
    }

    // reduce across the 8 parts of each query (8 consecutive lanes in a warp)
    #pragma unroll
    for (int off = 4; off >= 1; off >>= 1) {
        esum += __shfl_down_sync(0xffffffffu, esum, off);
        #pragma unroll
        for (int f = 0; f < DIM; f++)
            acc[f] += __shfl_down_sync(0xffffffffu, acc[f], off);
    }

    if (p == 0) {
        float inv = 1.0f / esum;
        #pragma unroll
        for (int f = 0; f < DIM; f++)
            out[(q0 + qi) * DIM + f] = acc[f] * inv;
    }
}

// ---------------------------------------------------------------------------
extern "C" void kernel_launch(void* const* d_in, const int* in_sizes, int n_in,
                              void* d_out, int out_size) {
    const float* x = (const float*)d_in[0];   // [8192, 3, 10]
    const float* A = (const float*)d_in[1];   // [3, 3]
    const float* W = (const float*)d_in[2];   // [10, 10]
    float* out = (float*)d_out;               // [8192, 10]

    pooled_kernel<<<BATCH / 256, 256>>>(x, A, W);
    attn_kernel<<<BATCH / BQ, NTHREADS>>>(out);
}